// round 1
// baseline (speedup 1.0000x reference)
#include <cuda_runtime.h>
#include <cstdint>

// Problem constants (fixed by the reference)
#define NNODES 100000
#define NEDGES 1600000
#define FIN    128
#define HID    64
#define NCLS   40

// ---------------- device scratch (allocation-free) ----------------
__device__ float g_deg[NNODES];          // degree of A + I
__device__ float g_dinv[NNODES];         // deg^{-1/2}
__device__ float g_h1[(size_t)NNODES * HID];    // x @ W1
__device__ float g_agg1[(size_t)NNODES * HID];  // aggregated layer-1 (pre-relu, bias folded)
__device__ float g_h2[(size_t)NNODES * NCLS];   // relu(agg1) @ W2

// ---------------- helpers ----------------
__device__ __forceinline__ void red_add_v4(float* addr, float a, float b, float c, float d) {
    asm volatile("red.global.add.v4.f32 [%0], {%1, %2, %3, %4};"
                 :: "l"(addr), "f"(a), "f"(b), "f"(c), "f"(d)
                 : "memory");
}

// ---------------- kernels ----------------

// deg[i] = 1 (self loop)
__global__ void k_init_deg() {
    int i = blockIdx.x * blockDim.x + threadIdx.x;
    if (i < NNODES) g_deg[i] = 1.0f;
}

// deg[dst[e]] += 1
__global__ void k_count_deg(const int* __restrict__ dst) {
    int e = blockIdx.x * blockDim.x + threadIdx.x;
    if (e < NEDGES) atomicAdd(&g_deg[dst[e]], 1.0f);
}

__global__ void k_dinv() {
    int i = blockIdx.x * blockDim.x + threadIdx.x;
    if (i < NNODES) g_dinv[i] = rsqrtf(g_deg[i]);
}

// H1 = x @ W1   (4 rows per 256-thread block; W1 in SMEM)
__global__ void k_gemm1(const float* __restrict__ x, const float* __restrict__ W1) {
    __shared__ float ws[FIN * HID];   // 32 KB
    __shared__ float xs[4 * FIN];     // 2 KB
    const int tid = threadIdx.x;
    for (int i = tid; i < FIN * HID; i += 256) ws[i] = W1[i];
    const int row0 = blockIdx.x * 4;
    // 4 rows * 128 floats = 128 float4
    const float4* xsrc = (const float4*)(x + (size_t)row0 * FIN);
    if (tid < 128) ((float4*)xs)[tid] = xsrc[tid];
    __syncthreads();

    const int r   = tid >> 6;
    const int col = tid & 63;
    const float* xr = xs + r * FIN;
    float acc = 0.0f;
#pragma unroll
    for (int k = 0; k < FIN; k++)
        acc = fmaf(xr[k], ws[k * HID + col], acc);
    g_h1[(size_t)(row0 + r) * HID + col] = acc;
}

// agg1[i][c] = H1[i][c] * dinv[i]^2 + b1[c]   (self-loop + bias folded)
__global__ void k_init_agg1(const float* __restrict__ b1) {
    int t = blockIdx.x * blockDim.x + threadIdx.x;
    if (t >= NNODES * HID) return;
    int i = t >> 6;        // / HID
    int c = t & 63;        // % HID
    float di = g_dinv[i];
    g_agg1[t] = g_h1[t] * di * di + b1[c];
}

// edge scatter layer 1: agg1[dst] += H1[src] * norm  (16 float4 groups / edge)
__global__ void k_scatter1(const int* __restrict__ src, const int* __restrict__ dst) {
    long long t = (long long)blockIdx.x * blockDim.x + threadIdx.x;
    if (t >= (long long)NEDGES * 16) return;
    int e = (int)(t >> 4);
    int g = (int)(t & 15);
    int s = src[e], d = dst[e];
    float norm = g_dinv[s] * g_dinv[d];
    float4 v = *(const float4*)(g_h1 + (size_t)s * HID + g * 4);
    red_add_v4(g_agg1 + (size_t)d * HID + g * 4,
               v.x * norm, v.y * norm, v.z * norm, v.w * norm);
}

// H2 = relu(agg1) @ W2   (relu fused into SMEM load; 4 rows per block)
__global__ void k_gemm2(const float* __restrict__ W2) {
    __shared__ float ws[HID * NCLS];  // 2560 floats
    __shared__ float hs[4 * HID];     // 256 floats
    const int tid = threadIdx.x;
    for (int i = tid; i < HID * NCLS; i += 256) ws[i] = W2[i];
    const int row0 = blockIdx.x * 4;
    hs[tid] = fmaxf(g_agg1[(size_t)row0 * HID + tid], 0.0f);
    __syncthreads();

    const int r   = tid >> 6;
    const int col = tid & 63;
    if (col < NCLS) {
        const float* hr = hs + r * HID;
        float acc = 0.0f;
#pragma unroll
        for (int k = 0; k < HID; k++)
            acc = fmaf(hr[k], ws[k * NCLS + col], acc);
        g_h2[(size_t)(row0 + r) * NCLS + col] = acc;
    }
}

// out[i][c] = H2[i][c] * dinv[i]^2 + b2[c]
__global__ void k_init_out(float* __restrict__ out, const float* __restrict__ b2) {
    int t = blockIdx.x * blockDim.x + threadIdx.x;
    if (t >= NNODES * NCLS) return;
    int i = t / NCLS;
    int c = t - i * NCLS;
    float di = g_dinv[i];
    out[t] = g_h2[t] * di * di + b2[c];
}

// edge scatter layer 2: out[dst] += H2[src] * norm  (10 float4 groups / edge)
__global__ void k_scatter2(const int* __restrict__ src, const int* __restrict__ dst,
                           float* __restrict__ out) {
    long long t = (long long)blockIdx.x * blockDim.x + threadIdx.x;
    if (t >= (long long)NEDGES * 10) return;
    int e = (int)(t / 10);
    int g = (int)(t - (long long)e * 10);
    int s = src[e], d = dst[e];
    float norm = g_dinv[s] * g_dinv[d];
    float4 v = *(const float4*)(g_h2 + (size_t)s * NCLS + g * 4);
    red_add_v4(out + (size_t)d * NCLS + g * 4,
               v.x * norm, v.y * norm, v.z * norm, v.w * norm);
}

// ---------------- launch ----------------
extern "C" void kernel_launch(void* const* d_in, const int* in_sizes, int n_in,
                              void* d_out, int out_size) {
    const float* x   = (const float*)d_in[0];   // [N, 128]
    const int*   ei  = (const int*)d_in[1];     // [2, E]
    const float* W1  = (const float*)d_in[2];   // [128, 64]
    const float* b1  = (const float*)d_in[3];   // [64]
    const float* W2  = (const float*)d_in[4];   // [64, 40]
    const float* b2  = (const float*)d_in[5];   // [40]
    float* out = (float*)d_out;                 // [N, 40]

    const int* src = ei;
    const int* dst = ei + NEDGES;

    // degrees + normalization
    k_init_deg<<<(NNODES + 255) / 256, 256>>>();
    k_count_deg<<<(NEDGES + 255) / 256, 256>>>(dst);
    k_dinv<<<(NNODES + 255) / 256, 256>>>();

    // layer 1
    k_gemm1<<<NNODES / 4, 256>>>(x, W1);
    k_init_agg1<<<(NNODES * HID + 255) / 256, 256>>>(b1);
    {
        long long tot = (long long)NEDGES * 16;
        k_scatter1<<<(unsigned)((tot + 255) / 256), 256>>>(src, dst);
    }

    // layer 2
    k_gemm2<<<NNODES / 4, 256>>>(W2);
    k_init_out<<<(NNODES * NCLS + 255) / 256, 256>>>(out, b2);
    {
        long long tot = (long long)NEDGES * 10;
        k_scatter2<<<(unsigned)((tot + 255) / 256), 256>>>(src, dst, out);
    }
}

// round 2
// speedup vs baseline: 1.4662x; 1.4662x over previous
#include <cuda_runtime.h>
#include <cstdint>

#define NNODES 100000
#define NEDGES 1600000
#define FIN    128
#define HID    64
#define NCLS   40

// ---------------- device scratch (allocation-free) ----------------
__device__ float g_deg[NNODES];
__device__ float g_dinv[NNODES];
__device__ float g_h1[(size_t)NNODES * HID];     // x @ W1
__device__ float g_agg1[(size_t)NNODES * HID];   // layer-1 agg (self-loop + bias folded)
__device__ float g_h2[(size_t)NNODES * NCLS];    // relu(agg1) @ W2

// ---------------- helpers ----------------
typedef unsigned long long u64;

__device__ __forceinline__ u64 ffma2(u64 a, u64 b, u64 c) {
    u64 d;
    asm("fma.rn.f32x2 %0, %1, %2, %3;" : "=l"(d) : "l"(a), "l"(b), "l"(c));
    return d;
}
__device__ __forceinline__ u64 pack2(float x) {
    u64 d;
    asm("mov.b64 %0, {%1, %1};" : "=l"(d) : "f"(x));
    return d;
}
union F2 { u64 u; float2 f; };
union W4 { float4 v; struct { u64 lo, hi; } u; };

__device__ __forceinline__ void red_add_v4(float* addr, float a, float b, float c, float d) {
    asm volatile("red.global.add.v4.f32 [%0], {%1, %2, %3, %4};"
                 :: "l"(addr), "f"(a), "f"(b), "f"(c), "f"(d)
                 : "memory");
}

// ---------------- degree / normalization ----------------
__global__ void k_init_deg() {
    int i = blockIdx.x * blockDim.x + threadIdx.x;
    if (i < NNODES) g_deg[i] = 1.0f;
}
__global__ void k_count_deg(const int* __restrict__ dst) {
    int e = blockIdx.x * blockDim.x + threadIdx.x;
    if (e < NEDGES) atomicAdd(&g_deg[dst[e]], 1.0f);
}
__global__ void k_dinv() {
    int i = blockIdx.x * blockDim.x + threadIdx.x;
    if (i < NNODES) g_dinv[i] = rsqrtf(g_deg[i]);
}

// ---------------- GEMM1: h1 = x @ W1 ; agg1 = h1*dinv^2 + b1 ----------------
// 256 threads, 64 rows/block, each thread: 2 rows x 8 cols via f32x2 FMA.
#define XS_PITCH 132   // 128 + 4 pad (conflict-free scalar/vec4 reads)
__global__ void __launch_bounds__(256) k_gemm1(const float* __restrict__ x,
                                               const float* __restrict__ W1,
                                               const float* __restrict__ b1) {
    __shared__ float xs[64 * XS_PITCH];  // 33 KB
    __shared__ float ws[FIN * HID];      // 32 KB
    const int tid  = threadIdx.x;
    const int row0 = blockIdx.x * 64;

    // load W1 (coalesced float4)
    {
        const float4* wsrc = (const float4*)W1;
        float4* wdst = (float4*)ws;
        #pragma unroll
        for (int i = 0; i < 8; i++) wdst[tid + i * 256] = wsrc[tid + i * 256];
    }
    // load x tile: 64 rows x 128 floats = 2048 float4, into pitched smem
    {
        #pragma unroll
        for (int i = 0; i < 8; i++) {
            int f = tid + i * 256;            // [0, 2048)
            int r = f >> 5;                   // f / 32
            int o = (f & 31) << 2;            // (f % 32) * 4
            float4 v = make_float4(0.f, 0.f, 0.f, 0.f);
            if (row0 + r < NNODES) v = *(const float4*)(x + (size_t)(row0 + r) * FIN + o);
            *(float4*)(xs + r * XS_PITCH + o) = v;
        }
    }
    __syncthreads();

    const int rp = tid >> 3;      // 0..31
    const int cg = tid & 7;       // 0..7
    const int r0 = rp * 2, r1 = r0 + 1;
    const float* xr0 = xs + r0 * XS_PITCH;
    const float* xr1 = xs + r1 * XS_PITCH;
    const float* wcol = ws + cg * 8;

    u64 acc[2][4];
    #pragma unroll
    for (int r = 0; r < 2; r++)
        #pragma unroll
        for (int j = 0; j < 4; j++) acc[r][j] = 0ull;

    #pragma unroll 4
    for (int k = 0; k < FIN; k += 4) {
        float4 xa = *(const float4*)(xr0 + k);
        float4 xb = *(const float4*)(xr1 + k);
        #pragma unroll
        for (int kk = 0; kk < 4; kk++) {
            u64 xa2 = pack2((&xa.x)[kk]);
            u64 xb2 = pack2((&xb.x)[kk]);
            W4 w0, w1;
            w0.v = *(const float4*)(wcol + (k + kk) * HID);
            w1.v = *(const float4*)(wcol + (k + kk) * HID + 4);
            acc[0][0] = ffma2(w0.u.lo, xa2, acc[0][0]);
            acc[0][1] = ffma2(w0.u.hi, xa2, acc[0][1]);
            acc[0][2] = ffma2(w1.u.lo, xa2, acc[0][2]);
            acc[0][3] = ffma2(w1.u.hi, xa2, acc[0][3]);
            acc[1][0] = ffma2(w0.u.lo, xb2, acc[1][0]);
            acc[1][1] = ffma2(w0.u.hi, xb2, acc[1][1]);
            acc[1][2] = ffma2(w1.u.lo, xb2, acc[1][2]);
            acc[1][3] = ffma2(w1.u.hi, xb2, acc[1][3]);
        }
    }

    // epilogue: write h1 and agg1 = h1*dinv^2 + b1
    float4 bb0 = *(const float4*)(b1 + cg * 8);
    float4 bb1 = *(const float4*)(b1 + cg * 8 + 4);
    #pragma unroll
    for (int r = 0; r < 2; r++) {
        int row = row0 + r0 + r;
        if (row >= NNODES) continue;
        float di = g_dinv[row];
        float dd = di * di;
        F2 a0, a1, a2, a3;
        a0.u = acc[r][0]; a1.u = acc[r][1]; a2.u = acc[r][2]; a3.u = acc[r][3];
        float4 o0 = make_float4(a0.f.x, a0.f.y, a1.f.x, a1.f.y);
        float4 o1 = make_float4(a2.f.x, a2.f.y, a3.f.x, a3.f.y);
        float* hp = g_h1 + (size_t)row * HID + cg * 8;
        *(float4*)(hp)     = o0;
        *(float4*)(hp + 4) = o1;
        float4 g0 = make_float4(fmaf(o0.x, dd, bb0.x), fmaf(o0.y, dd, bb0.y),
                                fmaf(o0.z, dd, bb0.z), fmaf(o0.w, dd, bb0.w));
        float4 g1 = make_float4(fmaf(o1.x, dd, bb1.x), fmaf(o1.y, dd, bb1.y),
                                fmaf(o1.z, dd, bb1.z), fmaf(o1.w, dd, bb1.w));
        float* ap = g_agg1 + (size_t)row * HID + cg * 8;
        *(float4*)(ap)     = g0;
        *(float4*)(ap + 4) = g1;
    }
}

// ---------------- scatter layer 1: agg1[dst] += h1[src]*norm ----------------
__global__ void k_scatter1(const int* __restrict__ src, const int* __restrict__ dst) {
    long long t = (long long)blockIdx.x * blockDim.x + threadIdx.x;
    if (t >= (long long)NEDGES * 16) return;
    int e = (int)(t >> 4);
    int g = (int)(t & 15);
    int s = src[e], d = dst[e];
    float norm = g_dinv[s] * g_dinv[d];
    float4 v = *(const float4*)(g_h1 + (size_t)s * HID + g * 4);
    red_add_v4(g_agg1 + (size_t)d * HID + g * 4,
               v.x * norm, v.y * norm, v.z * norm, v.w * norm);
}

// ---------------- GEMM2: h2 = relu(agg1) @ W2 ; out = h2*dinv^2 + b2 ----------------
// Same register-tiled structure; W2 padded 40 -> 64 cols with zeros in smem.
#define XS2_PITCH 68   // 64 + 4 pad
__global__ void __launch_bounds__(256) k_gemm2(const float* __restrict__ W2,
                                               const float* __restrict__ b2,
                                               float* __restrict__ out) {
    __shared__ float xs[64 * XS2_PITCH];  // 17.4 KB
    __shared__ float ws[HID * 64];        // 16 KB (padded cols)
    const int tid  = threadIdx.x;
    const int row0 = blockIdx.x * 64;

    // W2 [64][40] -> ws [64][64] zero-padded
    #pragma unroll
    for (int i = 0; i < 16; i++) {
        int idx = tid + i * 256;          // [0, 4096)
        int k = idx >> 6, c = idx & 63;
        ws[idx] = (c < NCLS) ? W2[k * NCLS + c] : 0.0f;
    }
    // relu(agg1) tile: 64 rows x 64 floats = 1024 float4
    #pragma unroll
    for (int i = 0; i < 4; i++) {
        int f = tid + i * 256;            // [0, 1024)
        int r = f >> 4;
        int o = (f & 15) << 2;
        float4 v = make_float4(0.f, 0.f, 0.f, 0.f);
        if (row0 + r < NNODES) {
            float4 a = *(const float4*)(g_agg1 + (size_t)(row0 + r) * HID + o);
            v = make_float4(fmaxf(a.x, 0.f), fmaxf(a.y, 0.f),
                            fmaxf(a.z, 0.f), fmaxf(a.w, 0.f));
        }
        *(float4*)(xs + r * XS2_PITCH + o) = v;
    }
    __syncthreads();

    const int rp = tid >> 3;
    const int cg = tid & 7;
    if (cg >= 5) return;                  // cols 40..63 are padding
    const int r0 = rp * 2, r1 = r0 + 1;
    const float* xr0 = xs + r0 * XS2_PITCH;
    const float* xr1 = xs + r1 * XS2_PITCH;
    const float* wcol = ws + cg * 8;

    u64 acc[2][4];
    #pragma unroll
    for (int r = 0; r < 2; r++)
        #pragma unroll
        for (int j = 0; j < 4; j++) acc[r][j] = 0ull;

    #pragma unroll 4
    for (int k = 0; k < HID; k += 4) {
        float4 xa = *(const float4*)(xr0 + k);
        float4 xb = *(const float4*)(xr1 + k);
        #pragma unroll
        for (int kk = 0; kk < 4; kk++) {
            u64 xa2 = pack2((&xa.x)[kk]);
            u64 xb2 = pack2((&xb.x)[kk]);
            W4 w0, w1;
            w0.v = *(const float4*)(wcol + (k + kk) * 64);
            w1.v = *(const float4*)(wcol + (k + kk) * 64 + 4);
            acc[0][0] = ffma2(w0.u.lo, xa2, acc[0][0]);
            acc[0][1] = ffma2(w0.u.hi, xa2, acc[0][1]);
            acc[0][2] = ffma2(w1.u.lo, xa2, acc[0][2]);
            acc[0][3] = ffma2(w1.u.hi, xa2, acc[0][3]);
            acc[1][0] = ffma2(w0.u.lo, xb2, acc[1][0]);
            acc[1][1] = ffma2(w0.u.hi, xb2, acc[1][1]);
            acc[1][2] = ffma2(w1.u.lo, xb2, acc[1][2]);
            acc[1][3] = ffma2(w1.u.hi, xb2, acc[1][3]);
        }
    }

    float4 bb0 = *(const float4*)(b2 + cg * 8);
    float4 bb1 = *(const float4*)(b2 + cg * 8 + 4);
    #pragma unroll
    for (int r = 0; r < 2; r++) {
        int row = row0 + r0 + r;
        if (row >= NNODES) continue;
        float di = g_dinv[row];
        float dd = di * di;
        F2 a0, a1, a2, a3;
        a0.u = acc[r][0]; a1.u = acc[r][1]; a2.u = acc[r][2]; a3.u = acc[r][3];
        float4 o0 = make_float4(a0.f.x, a0.f.y, a1.f.x, a1.f.y);
        float4 o1 = make_float4(a2.f.x, a2.f.y, a3.f.x, a3.f.y);
        float* hp = g_h2 + (size_t)row * NCLS + cg * 8;
        *(float4*)(hp)     = o0;
        *(float4*)(hp + 4) = o1;
        float4 g0 = make_float4(fmaf(o0.x, dd, bb0.x), fmaf(o0.y, dd, bb0.y),
                                fmaf(o0.z, dd, bb0.z), fmaf(o0.w, dd, bb0.w));
        float4 g1 = make_float4(fmaf(o1.x, dd, bb1.x), fmaf(o1.y, dd, bb1.y),
                                fmaf(o1.z, dd, bb1.z), fmaf(o1.w, dd, bb1.w));
        float* op = out + (size_t)row * NCLS + cg * 8;
        *(float4*)(op)     = g0;
        *(float4*)(op + 4) = g1;
    }
}

// ---------------- scatter layer 2: out[dst] += h2[src]*norm ----------------
__global__ void k_scatter2(const int* __restrict__ src, const int* __restrict__ dst,
                           float* __restrict__ out) {
    long long t = (long long)blockIdx.x * blockDim.x + threadIdx.x;
    if (t >= (long long)NEDGES * 10) return;
    int e = (int)(t / 10);
    int g = (int)(t - (long long)e * 10);
    int s = src[e], d = dst[e];
    float norm = g_dinv[s] * g_dinv[d];
    float4 v = *(const float4*)(g_h2 + (size_t)s * NCLS + g * 4);
    red_add_v4(out + (size_t)d * NCLS + g * 4,
               v.x * norm, v.y * norm, v.z * norm, v.w * norm);
}

// ---------------- launch ----------------
extern "C" void kernel_launch(void* const* d_in, const int* in_sizes, int n_in,
                              void* d_out, int out_size) {
    const float* x   = (const float*)d_in[0];
    const int*   ei  = (const int*)d_in[1];
    const float* W1  = (const float*)d_in[2];
    const float* b1  = (const float*)d_in[3];
    const float* W2  = (const float*)d_in[4];
    const float* b2  = (const float*)d_in[5];
    float* out = (float*)d_out;

    const int* src = ei;
    const int* dst = ei + NEDGES;

    k_init_deg<<<(NNODES + 255) / 256, 256>>>();
    k_count_deg<<<(NEDGES + 255) / 256, 256>>>(dst);
    k_dinv<<<(NNODES + 255) / 256, 256>>>();

    const int gemm_grid = (NNODES + 63) / 64;   // 1563
    k_gemm1<<<gemm_grid, 256>>>(x, W1, b1);
    {
        long long tot = (long long)NEDGES * 16;
        k_scatter1<<<(unsigned)((tot + 255) / 256), 256>>>(src, dst);
    }
    k_gemm2<<<gemm_grid, 256>>>(W2, b2, out);
    {
        long long tot = (long long)NEDGES * 10;
        k_scatter2<<<(unsigned)((tot + 255) / 256), 256>>>(src, dst, out);
    }
}